// round 13
// baseline (speedup 1.0000x reference)
#include <cuda_runtime.h>
#include <cuda_fp16.h>
#include <mma.h>
#include <cstdint>

using namespace nvcuda;

// Problem dims
#define BT   512
#define BB   128
#define II   512
#define HH   1024
#define TGTD 128
#define MROWS (BT*BB)

#define NBLK 128            // persistent recurrence CTAs (64 per direction)
#define DIRCTA 64

// ---------------- scratch (static device memory; no allocation) ----------------
__device__ float  g_h  [2][BB][HH];            // master hidden state (fp32)
__device__ __half g_hh [2][BB][HH];            // fp16 mirror of h
__device__ __half g_rhh[2][BB][HH];            // r*h (fp16)
__device__ float  g_u  [2][BB][HH];            // update gate (fp32)
__device__ __half g_xh [2][BB*BT*II];          // fp16 inputs
__device__ __half g_wh [2][3][II*HH];          // fp16 input weights
__device__ __half g_woh[2*HH*TGTD];            // fp16 output weights
__device__ __half g_xp [2][3][MROWS][HH];      // input projections (+bias), fp16
__device__ __half g_hcat[MROWS][2*HH];         // concatenated hiddens, fp16

__device__ unsigned g_cnt[2][32];              // per-direction barrier counters (padded)
__device__ unsigned g_epd[2][32];              // per-direction epochs (padded)

__device__ __forceinline__ float sigmoidf_(float x) { return 1.0f / (1.0f + __expf(-x)); }

// ---------------- cp.async helpers ----------------
__device__ __forceinline__ void cpa16(uint32_t dst_smem, const void* src)
{
    asm volatile("cp.async.cg.shared.global [%0], [%1], 16;\n" :: "r"(dst_smem), "l"(src));
}
__device__ __forceinline__ void cpa_commit()
{
    asm volatile("cp.async.commit_group;\n" ::);
}
template<int N>
__device__ __forceinline__ void cpa_wait()
{
    asm volatile("cp.async.wait_group %0;\n" :: "n"(N));
}

// ---------------- per-direction grid barrier (64 CTAs, acq/rel) ----------------
__device__ __forceinline__ void dir_barrier(int d)
{
    __syncthreads();
    if (threadIdx.x == 0) {
        unsigned e;
        asm volatile("ld.relaxed.gpu.u32 %0, [%1];" : "=r"(e) : "l"(&g_epd[d][0]));
        unsigned old;
        asm volatile("atom.acq_rel.gpu.add.u32 %0, [%1], %2;"
                     : "=r"(old) : "l"(&g_cnt[d][0]), "r"(1u) : "memory");
        if (old == DIRCTA - 1) {
            asm volatile("st.relaxed.gpu.u32 [%0], %1;" :: "l"(&g_cnt[d][0]), "r"(0u) : "memory");
            asm volatile("st.release.gpu.u32 [%0], %1;" :: "l"(&g_epd[d][0]), "r"(e + 1u) : "memory");
        } else {
            unsigned v;
            do {
                __nanosleep(16);
                asm volatile("ld.acquire.gpu.u32 %0, [%1];" : "=r"(v) : "l"(&g_epd[d][0]) : "memory");
            } while (v == e);
        }
    }
    __syncthreads();
}

// ---------------- fp16 GEMM core for proj / head (128 x 128 tile, BK=32) ----------------
#define GEMM128_SMEM 69632
template<typename RowPtrF, typename EpiF>
__device__ __forceinline__ void gemm128(int K, RowPtrF rowA, const __half* Bp, int ldb,
                                        EpiF epi)
{
    extern __shared__ __align__(16) char dsm[];
    __half (*sA)[128][40]  = reinterpret_cast<__half (*)[128][40]>(dsm);
    __half (*sB)[32][136]  = reinterpret_cast<__half (*)[32][136]>(dsm + 2 * 128 * 40 * 2);
    float  (*sE)[136]      = reinterpret_cast<float (*)[136]>(dsm);

    const int tid = threadIdx.x;
    const int wid = tid >> 5;
    const int wm0 = (wid & 3) * 32;
    const int wn0 = (wid >> 2) * 64;

    wmma::fragment<wmma::accumulator, 16, 16, 16, float> acc[2][4];
#pragma unroll
    for (int i = 0; i < 2; i++)
#pragma unroll
        for (int j = 0; j < 4; j++) wmma::fill_fragment(acc[i][j], 0.0f);

    const int a_row = tid >> 1;
    const int aq = (tid & 1) * 16;
    const __half* arp = rowA(a_row) + aq;
    const int b_row = tid >> 3;
    const int bq = (tid & 7) * 16;
    const __half* brp = Bp + (size_t)b_row * ldb + bq;

    uint4 av0 = *(const uint4*)arp;
    uint4 av1 = *(const uint4*)(arp + 8);
    uint4 bv0 = *(const uint4*)brp;
    uint4 bv1 = *(const uint4*)(brp + 8);

    const int nIter = K / 32;
    for (int it = 0; it < nIter; ++it) {
        const int p = it & 1;
        *(uint4*)&sA[p][a_row][aq]     = av0;
        *(uint4*)&sA[p][a_row][aq + 8] = av1;
        *(uint4*)&sB[p][b_row][bq]     = bv0;
        *(uint4*)&sB[p][b_row][bq + 8] = bv1;
        __syncthreads();
        if (it + 1 < nIter) {
            const int k0 = (it + 1) * 32;
            av0 = *(const uint4*)(arp + k0);
            av1 = *(const uint4*)(arp + k0 + 8);
            bv0 = *(const uint4*)(brp + (size_t)k0 * ldb);
            bv1 = *(const uint4*)(brp + (size_t)k0 * ldb + 8);
        }
#pragma unroll
        for (int ks = 0; ks < 32; ks += 16) {
            wmma::fragment<wmma::matrix_a, 16, 16, 16, __half, wmma::row_major> af[2];
            wmma::fragment<wmma::matrix_b, 16, 16, 16, __half, wmma::row_major> bf[4];
#pragma unroll
            for (int i = 0; i < 2; i++)
                wmma::load_matrix_sync(af[i], &sA[p][wm0 + i * 16][ks], 40);
#pragma unroll
            for (int j = 0; j < 4; j++)
                wmma::load_matrix_sync(bf[j], &sB[p][ks][wn0 + j * 16], 136);
#pragma unroll
            for (int i = 0; i < 2; i++)
#pragma unroll
                for (int j = 0; j < 4; j++)
                    wmma::mma_sync(acc[i][j], af[i], bf[j], acc[i][j]);
        }
        __syncthreads();
    }

#pragma unroll
    for (int i = 0; i < 2; i++)
#pragma unroll
        for (int j = 0; j < 4; j++)
            wmma::store_matrix_sync(&sE[wm0 + i * 16][wn0 + j * 16], acc[i][j], 136,
                                    wmma::mem_row_major);
    __syncthreads();
#pragma unroll
    for (int e = 0; e < 64; e++) {
        const int idx = tid + e * 256;
        const int m = idx >> 7;
        const int n = idx & 127;
        epi(m, n, sE[m][n]);
    }
}

// ---------------- recurrence phase GEMM with cp.async pipeline ----------------
// A: [128 x 1024] fp16 global, B: [1024 x NC] fp16 resident smem with padded
// row stride LDW (conflict-breaking). 4-stage pipeline over A.
// Caller must have issued exactly ONE cp.async group (epilogue operands) before calling.
#define STG_H (128 * 72)          // halves per stage
template<int NC, int LDW, int MFRAG, typename EpiF>
__device__ __forceinline__ void rec_phase(const __half* __restrict__ Aglob,
                                          const __half* __restrict__ sW,
                                          __half* __restrict__ sA,
                                          float* __restrict__ sE,
                                          EpiF epi)
{
    const int tid = threadIdx.x;
    const int wid = tid >> 5;
    const int wm0 = (MFRAG == 2) ? (wid & 3) * 32 : wid * 16;
    const int wn0 = (MFRAG == 2) ? (wid >> 2) * 16 : 0;

    wmma::fragment<wmma::accumulator, 16, 16, 16, float> acc[MFRAG];
#pragma unroll
    for (int i = 0; i < MFRAG; i++) wmma::fill_fragment(acc[i], 0.0f);

    const int r  = tid >> 3;          // 0..31
    const int c8 = (tid & 7) * 8;     // halves
    const uint32_t sA_base = (uint32_t)__cvta_generic_to_shared(sA);

    auto issue_stage = [&](int j) {
        const uint32_t stg = sA_base + (uint32_t)(j & 3) * (STG_H * 2);
#pragma unroll
        for (int i = 0; i < 4; i++) {
            const int row = r + 32 * i;
            cpa16(stg + (uint32_t)(row * 72 + c8) * 2,
                  Aglob + (size_t)row * HH + j * 64 + c8);
        }
    };

    // prologue: stages 0..2
    issue_stage(0); cpa_commit();
    issue_stage(1); cpa_commit();
    issue_stage(2); cpa_commit();

    for (int it = 0; it < 16; ++it) {
        cpa_wait<2>();
        __syncthreads();
        if (it + 3 < 16) issue_stage(it + 3);
        cpa_commit();                         // commit every iter (possibly empty)
        const __half* Ab = sA + (it & 3) * STG_H;
#pragma unroll
        for (int ks = 0; ks < 64; ks += 16) {
            wmma::fragment<wmma::matrix_a, 16, 16, 16, __half, wmma::row_major> af[MFRAG];
            wmma::fragment<wmma::matrix_b, 16, 16, 16, __half, wmma::row_major> bf;
#pragma unroll
            for (int i = 0; i < MFRAG; i++)
                wmma::load_matrix_sync(af[i], Ab + (wm0 + 16 * i) * 72 + ks, 72);
            wmma::load_matrix_sync(bf, sW + (it * 64 + ks) * LDW + wn0, LDW);
#pragma unroll
            for (int i = 0; i < MFRAG; i++)
                wmma::mma_sync(acc[i], af[i], bf, acc[i]);
        }
    }
    cpa_wait<0>();
    __syncthreads();
#pragma unroll
    for (int i = 0; i < MFRAG; i++)
        wmma::store_matrix_sync(sE + (wm0 + 16 * i) * (NC + 4) + wn0, acc[i], NC + 4,
                                wmma::mem_row_major);
    __syncthreads();
#pragma unroll
    for (int e = 0; e < (128 * NC) / 256; e++) {
        const int idx = tid + e * 256;
        const int m = idx / NC;
        const int n = idx % NC;
        epi(m, n, sE[m * (NC + 4) + n]);
    }
    __syncthreads();
}

// ---------------- kernels ----------------

__global__ void zero_h_kernel()
{
    int i = blockIdx.x * blockDim.x + threadIdx.x;
    ((float*)g_h)[i] = 0.0f;
    ((__half*)g_hh)[i] = __float2half(0.0f);
}

struct alignas(8) H4 { __half2 a, b; };
__device__ __forceinline__ H4 f2h4(float4 vv)
{
    H4 o;
    o.a = __floats2half2_rn(vv.x, vv.y);
    o.b = __floats2half2_rn(vv.z, vv.w);
    return o;
}

#define NX4 ((BB * BT * II) / 4)     // 8388608 float4 per direction input
#define NW4 ((II * HH) / 4)          // 131072 float4 per W matrix
#define NO4 ((2 * HH * TGTD) / 4)    // 65536 float4 for Wo

struct ConvArgs {
    const float4* x[2];
    const float4* w[6];
    const float4* wo;
};

// one fused conversion kernel: inputs, input weights, output weights
__global__ void conv_all_kernel(ConvArgs c)
{
    long i = (long)blockIdx.x * blockDim.x + threadIdx.x;
    if (i < 2L * NX4) {
        const int dir = i >= NX4;
        const long k = i - (long)dir * NX4;
        ((H4*)&g_xh[dir][0])[k] = f2h4(c.x[dir][k]);
    } else if (i < 2L * NX4 + 6L * NW4) {
        const long j = i - 2L * NX4;
        const int slot = (int)(j / NW4);
        const long k = j % NW4;
        ((H4*)&g_wh[slot / 3][slot % 3][0])[k] = f2h4(c.w[slot][k]);
    } else {
        const long k = i - 2L * NX4 - 6L * NW4;
        ((H4*)&g_woh[0])[k] = f2h4(c.wo[k]);
    }
}

__global__ void dummy_kernel() {}

struct ProjArgs { const float* bias[2][3]; };

// grid (24, 512, 2): 128x128 tiles over [65536 x 3072]
__global__ void __launch_bounds__(256) proj_kernel(ProjArgs a)
{
    const int d  = blockIdx.z;
    const int m0 = blockIdx.y * 128;
    const int n0 = blockIdx.x * 128;
    const int g  = n0 >> 10;
    const int nb = n0 & 1023;
    const __half* X  = g_xh[d];
    const __half* Bp = g_wh[d][g] + nb;
    const float*  bs = a.bias[d][g];

    auto rowA = [&](int m) -> const __half* {
        const int rr = m0 + m;
        const int t = rr >> 7;
        const int b = rr & 127;
        return X + ((size_t)b * BT + t) * II;
    };
    auto epi = [&](int m, int n, float vv) {
        const int rr = m0 + m;
        const int c = nb + n;
        g_xp[d][g][rr][c] = __float2half(vv + bs[c]);
    };
    gemm128(II, rowA, Bp, HH, epi);
}

struct RecArgs { const float* U[2][2]; const float* Uh[2]; };

// Dynamic smem layout for recur_kernel:
//   [0      , 81920 )  sW1: 1024 x 32 fp16, padded row stride 40 halves
//   [81920  , 131072)  sW2: 1024 x 16 fp16, padded row stride 24 halves
//   [131072 , 204800)  sA : 4 stages x 128 x 72 fp16   (sE fp32 staging aliases here)
//   [204800 , 212992)  sX : xg/xh tile
//   [212992 , 221184)  sY : hh tile (phase1) / u tile fp32 (phase2)
//   [221184 , 229376)  sZ : h tile fp32 (phase2)
#define REC_SMEM 229376
__global__ void __launch_bounds__(256) recur_kernel(RecArgs a)
{
    extern __shared__ __align__(16) char rsm[];
    __half* sW1 = (__half*)rsm;
    __half* sW2 = (__half*)(rsm + 81920);
    __half* sA  = (__half*)(rsm + 131072);
    float*  sE  = (float*)(rsm + 131072);
    __half* sXh = (__half*)(rsm + 204800);
    __half* sYh = (__half*)(rsm + 212992);
    float*  sU  = (float*)(rsm + 212992);
    float*  sHf = (float*)(rsm + 221184);

    const uint32_t sX_a = (uint32_t)__cvta_generic_to_shared(sXh);
    const uint32_t sY_a = (uint32_t)__cvta_generic_to_shared(sYh);
    const uint32_t sZ_a = (uint32_t)__cvta_generic_to_shared(sHf);

    const int tid = threadIdx.x;
    const int s = blockIdx.x & 63;
    const int d = blockIdx.x >> 6;
    const int g1 = s >> 5;                             // phase1 gate (0=r,1=u)
    const int col0 = (s & 31) * 32;                    // phase1 col base
    const int col2 = s * 16;                           // phase2 col base

    // Load weight slices into smem (fp32 -> fp16), once. Padded strides.
    {
        const float* src1 = a.U[d][g1];
#pragma unroll
        for (int i = 0; i < 32; i++) {
            const int idx = tid + i * 256;
            const int k = idx >> 3, q = idx & 7;
            float4 w = *(const float4*)(src1 + (size_t)k * HH + col0 + q * 4);
            *(__half2*)(sW1 + k * 40 + q * 4)     = __floats2half2_rn(w.x, w.y);
            *(__half2*)(sW1 + k * 40 + q * 4 + 2) = __floats2half2_rn(w.z, w.w);
        }
        const float* src2 = a.Uh[d];
#pragma unroll
        for (int i = 0; i < 16; i++) {
            const int idx = tid + i * 256;
            const int k = idx >> 2, q = idx & 3;
            float4 w = *(const float4*)(src2 + (size_t)k * HH + col2 + q * 4);
            *(__half2*)(sW2 + k * 24 + q * 4)     = __floats2half2_rn(w.x, w.y);
            *(__half2*)(sW2 + k * 24 + q * 4 + 2) = __floats2half2_rn(w.z, w.w);
        }
    }
    __syncthreads();

    for (int t = 0; t < BT; ++t) {
        {   // ---- phase 1 ----
            const __half* xg = &g_xp[d][g1][(size_t)t * BB][0];
            // epilogue operand prefetch (group 0): xg tile, hh tile (gate r only)
            {
#pragma unroll
                for (int rep = 0; rep < 2; rep++) {
                    const int idx = tid + rep * 256;
                    const int row = idx >> 2, q = idx & 3;
                    cpa16(sX_a + (uint32_t)(row * 64 + q * 16),
                          xg + (size_t)row * HH + col0 + q * 8);
                    if (g1 == 0)
                        cpa16(sY_a + (uint32_t)(row * 64 + q * 16),
                              &g_hh[d][row][col0] + q * 8);
                }
                cpa_commit();
            }
            auto epi = [&](int m, int n, float vv) {
                const int c = col0 + n;
                const float sg = sigmoidf_(__half2float(sXh[m * 32 + n]) + vv);
                if (g1 == 0)
                    g_rhh[d][m][c] = __float2half(sg * __half2float(sYh[m * 32 + n]));
                else
                    g_u[d][m][c] = sg;
            };
            rec_phase<32, 40, 2>(&g_hh[d][0][0], sW1, sA, sE, epi);
        }
        dir_barrier(d);
        {   // ---- phase 2 ----
            const __half* xh = &g_xp[d][2][(size_t)t * BB][0];
            {   // prefetch xh (128x16 fp16), u (128x16 fp32), h (128x16 fp32)
                {
                    const int row = tid >> 1, q = tid & 1;
                    cpa16(sX_a + (uint32_t)(row * 32 + q * 16),
                          xh + (size_t)row * HH + col2 + q * 8);
                }
#pragma unroll
                for (int rep = 0; rep < 2; rep++) {
                    const int idx = tid + rep * 256;
                    const int row = idx >> 2, q = idx & 3;
                    cpa16(sY_a + (uint32_t)(row * 64 + q * 16),
                          &g_u[d][row][col2] + q * 4);
                    cpa16(sZ_a + (uint32_t)(row * 64 + q * 16),
                          &g_h[d][row][col2] + q * 4);
                }
                cpa_commit();
            }
            auto epi = [&](int m, int n, float vv) {
                const int c = col2 + n;
                const float cand = tanhf(__half2float(sXh[m * 16 + n]) + vv);
                const float uu = sU[m * 16 + n];
                const float hp = sHf[m * 16 + n];
                const float hn = uu * hp + (1.0f - uu) * cand;
                g_h[d][m][c] = hn;
                const __half hhv = __float2half(hn);
                g_hh[d][m][c] = hhv;
                g_hcat[(size_t)t * BB + m][d * HH + c] = hhv;
            };
            rec_phase<16, 24, 1>(&g_rhh[d][0][0], sW2, sA, sE, epi);
        }
        dir_barrier(d);
    }
}

// grid (1, 512)
__global__ void __launch_bounds__(256) out_kernel(const float* __restrict__ bo,
                                                  float* __restrict__ out)
{
    const int m0 = blockIdx.y * 128;
    const __half* Bp = g_woh;

    auto rowA = [&](int m) -> const __half* { return &g_hcat[m0 + m][0]; };
    auto epi = [&](int m, int n, float vv) {
        out[(size_t)(m0 + m) * TGTD + n] = sigmoidf_(vv + bo[n]);
    };
    gemm128(2 * HH, rowA, Bp, TGTD, epi);
}

// ---------------- launch ----------------
extern "C" void kernel_launch(void* const* d_in, const int* in_sizes, int n_in,
                              void* d_out, int out_size)
{
    (void)in_sizes; (void)n_in; (void)out_size;
    const float* fwd = (const float*)d_in[0];
    const float* bwd = (const float*)d_in[1];
    const float* Wr  = (const float*)d_in[2];
    const float* Ur  = (const float*)d_in[3];
    const float* br  = (const float*)d_in[4];
    const float* Wu  = (const float*)d_in[5];
    const float* Uu  = (const float*)d_in[6];
    const float* bu  = (const float*)d_in[7];
    const float* Wh  = (const float*)d_in[8];
    const float* Uh  = (const float*)d_in[9];
    const float* bh  = (const float*)d_in[10];
    const float* Wr1 = (const float*)d_in[11];
    const float* Ur1 = (const float*)d_in[12];
    const float* br1 = (const float*)d_in[13];
    const float* Wu1 = (const float*)d_in[14];
    const float* Uu1 = (const float*)d_in[15];
    const float* bu1 = (const float*)d_in[16];
    const float* Wh1 = (const float*)d_in[17];
    const float* Uh1 = (const float*)d_in[18];
    const float* bh1 = (const float*)d_in[19];
    const float* Wo  = (const float*)d_in[20];
    const float* bo  = (const float*)d_in[21];
    float* out = (float*)d_out;

    static bool attr_done = false;
    if (!attr_done) {
        cudaFuncSetAttribute(recur_kernel, cudaFuncAttributeMaxDynamicSharedMemorySize,
                             REC_SMEM);
        cudaFuncSetAttribute(proj_kernel, cudaFuncAttributeMaxDynamicSharedMemorySize,
                             GEMM128_SMEM);
        cudaFuncSetAttribute(out_kernel, cudaFuncAttributeMaxDynamicSharedMemorySize,
                             GEMM128_SMEM);
        attr_done = true;
    }

    // launch #2 overall (harness issues one internal launch first)
    zero_h_kernel<<<(2 * BB * HH) / 1024, 1024>>>();

    // launch #3: fused conversions
    {
        ConvArgs c;
        c.x[0] = (const float4*)fwd;
        c.x[1] = (const float4*)bwd;
        c.w[0] = (const float4*)Wr;  c.w[1] = (const float4*)Wu;  c.w[2] = (const float4*)Wh;
        c.w[3] = (const float4*)Wr1; c.w[4] = (const float4*)Wu1; c.w[5] = (const float4*)Wh1;
        c.wo = (const float4*)Wo;
        const long total = 2L * NX4 + 6L * NW4 + NO4;   // 17629184
        conv_all_kernel<<<(unsigned)(total / 256), 256>>>(c);
    }

    // launch #4
    ProjArgs pa;
    pa.bias[0][0] = br;  pa.bias[0][1] = bu;  pa.bias[0][2] = bh;
    pa.bias[1][0] = br1; pa.bias[1][1] = bu1; pa.bias[1][2] = bh1;
    proj_kernel<<<dim3(3 * HH / 128, MROWS / 128, 2), 256, GEMM128_SMEM>>>(pa);

    // launch #5: single dummy so recur_kernel is overall launch #6 (ncu -s 5 -c 1)
    dummy_kernel<<<1, 32>>>();

    // launch #6: the recurrence (profiled)
    RecArgs ra;
    ra.U[0][0] = Ur;  ra.U[0][1] = Uu;
    ra.U[1][0] = Ur1; ra.U[1][1] = Uu1;
    ra.Uh[0] = Uh; ra.Uh[1] = Uh1;
    recur_kernel<<<NBLK, 256, REC_SMEM>>>(ra);

    // launch #7
    out_kernel<<<dim3(1, MROWS / 128, 1), 256, GEMM128_SMEM>>>(bo, out);
}

// round 14
// speedup vs baseline: 1.0231x; 1.0231x over previous
#include <cuda_runtime.h>
#include <cuda_fp16.h>
#include <mma.h>
#include <cstdint>

using namespace nvcuda;

// Problem dims
#define BT   512
#define BB   128
#define II   512
#define HH   1024
#define TGTD 128
#define MROWS (BT*BB)

#define NBLK 128            // persistent recurrence CTAs (64 per direction)
#define DIRCTA 64

// ---------------- scratch (static device memory; no allocation) ----------------
__device__ float  g_h  [2][BB][HH];            // master hidden state (fp32)
__device__ __half g_hh [2][BB][HH];            // fp16 mirror of h
__device__ __half g_rhh[2][BB][HH];            // r*h (fp16)
__device__ float  g_u  [2][BB][HH];            // update gate (fp32)
__device__ __half g_xh [2][BB*BT*II];          // fp16 inputs
__device__ __half g_wh [2][3][II*HH];          // fp16 input weights
__device__ __half g_woh[2*HH*TGTD];            // fp16 output weights
__device__ __half g_xp [2][3][MROWS][HH];      // input projections (+bias), fp16
__device__ __half g_hcat[MROWS][2*HH];         // concatenated hiddens, fp16

__device__ unsigned g_cnt[2][32];              // per-direction barrier counters (padded)
__device__ unsigned g_epd[2][32];              // per-direction epochs (padded)

__device__ __forceinline__ float sigmoidf_(float x) { return 1.0f / (1.0f + __expf(-x)); }

// ---------------- cp.async helpers ----------------
__device__ __forceinline__ void cpa16(uint32_t dst_smem, const void* src)
{
    asm volatile("cp.async.cg.shared.global [%0], [%1], 16;\n" :: "r"(dst_smem), "l"(src));
}
__device__ __forceinline__ void cpa_commit()
{
    asm volatile("cp.async.commit_group;\n" ::);
}
template<int N>
__device__ __forceinline__ void cpa_wait()
{
    asm volatile("cp.async.wait_group %0;\n" :: "n"(N));
}

// ---------------- per-direction grid barrier (64 CTAs, acq/rel) ----------------
__device__ __forceinline__ void dir_barrier(int d)
{
    __syncthreads();
    if (threadIdx.x == 0) {
        unsigned e;
        asm volatile("ld.relaxed.gpu.u32 %0, [%1];" : "=r"(e) : "l"(&g_epd[d][0]));
        unsigned old;
        asm volatile("atom.acq_rel.gpu.add.u32 %0, [%1], %2;"
                     : "=r"(old) : "l"(&g_cnt[d][0]), "r"(1u) : "memory");
        if (old == DIRCTA - 1) {
            asm volatile("st.relaxed.gpu.u32 [%0], %1;" :: "l"(&g_cnt[d][0]), "r"(0u) : "memory");
            asm volatile("st.release.gpu.u32 [%0], %1;" :: "l"(&g_epd[d][0]), "r"(e + 1u) : "memory");
        } else {
            unsigned v;
            do {
                __nanosleep(16);
                asm volatile("ld.acquire.gpu.u32 %0, [%1];" : "=r"(v) : "l"(&g_epd[d][0]) : "memory");
            } while (v == e);
        }
    }
    __syncthreads();
}

// ---------------- fp16 GEMM core for proj / head (128x128 tile, BK=32, cp.async) ----------------
// Dynamic smem: 4 A-stages (128x40 fp16 = 10240B) + 4 B-stages (32x136 fp16 = 8704B)
//             = 40960 + 34816 = 75776; fp32 epilogue staging [128][136] = 69632 aliases base.
#define GEMM128_SMEM 75776
template<typename RowPtrF, typename EpiF>
__device__ __forceinline__ void gemm128(int K, RowPtrF rowA, const __half* Bp, int ldb,
                                        EpiF epi)
{
    extern __shared__ __align__(16) char dsm[];
    float (*sE)[136] = reinterpret_cast<float (*)[136]>(dsm);

    const int tid = threadIdx.x;
    const int wid = tid >> 5;
    const int wm0 = (wid & 3) * 32;
    const int wn0 = (wid >> 2) * 64;

    wmma::fragment<wmma::accumulator, 16, 16, 16, float> acc[2][4];
#pragma unroll
    for (int i = 0; i < 2; i++)
#pragma unroll
        for (int j = 0; j < 4; j++) wmma::fill_fragment(acc[i][j], 0.0f);

    const uint32_t smA = (uint32_t)__cvta_generic_to_shared(dsm);
    const uint32_t smB = smA + 40960;

    auto issue_stage = [&](int j) {
        const uint32_t stA = smA + (uint32_t)(j & 3) * 10240;
        const uint32_t stB = smB + (uint32_t)(j & 3) * 8704;
#pragma unroll
        for (int e = 0; e < 2; e++) {
            const int idx = tid + e * 256;          // 0..511
            const int arow = idx >> 2, aq = idx & 3;
            cpa16(stA + (uint32_t)(arow * 80 + aq * 16),
                  rowA(arow) + j * 32 + aq * 8);
            const int brow = idx >> 4, bq = idx & 15;
            cpa16(stB + (uint32_t)(brow * 272 + bq * 16),
                  Bp + (size_t)(j * 32 + brow) * ldb + bq * 8);
        }
    };

    issue_stage(0); cpa_commit();
    issue_stage(1); cpa_commit();
    issue_stage(2); cpa_commit();

    const int nIter = K / 32;
    for (int it = 0; it < nIter; ++it) {
        cpa_wait<2>();
        __syncthreads();
        if (it + 3 < nIter) issue_stage(it + 3);
        cpa_commit();                       // commit every iter (possibly empty)
        const __half* Ab = (const __half*)dsm + (it & 3) * 5120;
        const __half* Bb = (const __half*)(dsm + 40960) + (it & 3) * 4352;
#pragma unroll
        for (int ks = 0; ks < 32; ks += 16) {
            wmma::fragment<wmma::matrix_a, 16, 16, 16, __half, wmma::row_major> af[2];
            wmma::fragment<wmma::matrix_b, 16, 16, 16, __half, wmma::row_major> bf[4];
#pragma unroll
            for (int i = 0; i < 2; i++)
                wmma::load_matrix_sync(af[i], Ab + (wm0 + i * 16) * 40 + ks, 40);
#pragma unroll
            for (int j = 0; j < 4; j++)
                wmma::load_matrix_sync(bf[j], Bb + ks * 136 + wn0 + j * 16, 136);
#pragma unroll
            for (int i = 0; i < 2; i++)
#pragma unroll
                for (int j = 0; j < 4; j++)
                    wmma::mma_sync(acc[i][j], af[i], bf[j], acc[i][j]);
        }
    }
    cpa_wait<0>();
    __syncthreads();

#pragma unroll
    for (int i = 0; i < 2; i++)
#pragma unroll
        for (int j = 0; j < 4; j++)
            wmma::store_matrix_sync(&sE[wm0 + i * 16][wn0 + j * 16], acc[i][j], 136,
                                    wmma::mem_row_major);
    __syncthreads();
#pragma unroll
    for (int e = 0; e < 64; e++) {
        const int idx = tid + e * 256;
        const int m = idx >> 7;
        const int n = idx & 127;
        epi(m, n, sE[m][n]);
    }
}

// ---------------- recurrence phase GEMM with cp.async pipeline ----------------
// A: [128 x 1024] fp16 global, B: [1024 x NC] fp16 resident smem with padded
// row stride LDW (conflict-breaking). 4-stage pipeline over A.
// Caller must have issued exactly ONE cp.async group (epilogue operands) before calling.
#define STG_H (128 * 72)          // halves per stage
template<int NC, int LDW, int MFRAG, typename EpiF>
__device__ __forceinline__ void rec_phase(const __half* __restrict__ Aglob,
                                          const __half* __restrict__ sW,
                                          __half* __restrict__ sA,
                                          float* __restrict__ sE,
                                          EpiF epi)
{
    const int tid = threadIdx.x;
    const int wid = tid >> 5;
    const int wm0 = (MFRAG == 2) ? (wid & 3) * 32 : wid * 16;
    const int wn0 = (MFRAG == 2) ? (wid >> 2) * 16 : 0;

    wmma::fragment<wmma::accumulator, 16, 16, 16, float> acc[MFRAG];
#pragma unroll
    for (int i = 0; i < MFRAG; i++) wmma::fill_fragment(acc[i], 0.0f);

    const int r  = tid >> 3;          // 0..31
    const int c8 = (tid & 7) * 8;     // halves
    const uint32_t sA_base = (uint32_t)__cvta_generic_to_shared(sA);

    auto issue_stage = [&](int j) {
        const uint32_t stg = sA_base + (uint32_t)(j & 3) * (STG_H * 2);
#pragma unroll
        for (int i = 0; i < 4; i++) {
            const int row = r + 32 * i;
            cpa16(stg + (uint32_t)(row * 72 + c8) * 2,
                  Aglob + (size_t)row * HH + j * 64 + c8);
        }
    };

    // prologue: stages 0..2
    issue_stage(0); cpa_commit();
    issue_stage(1); cpa_commit();
    issue_stage(2); cpa_commit();

    for (int it = 0; it < 16; ++it) {
        cpa_wait<2>();
        __syncthreads();
        if (it + 3 < 16) issue_stage(it + 3);
        cpa_commit();                         // commit every iter (possibly empty)
        const __half* Ab = sA + (it & 3) * STG_H;
#pragma unroll
        for (int ks = 0; ks < 64; ks += 16) {
            wmma::fragment<wmma::matrix_a, 16, 16, 16, __half, wmma::row_major> af[MFRAG];
            wmma::fragment<wmma::matrix_b, 16, 16, 16, __half, wmma::row_major> bf;
#pragma unroll
            for (int i = 0; i < MFRAG; i++)
                wmma::load_matrix_sync(af[i], Ab + (wm0 + 16 * i) * 72 + ks, 72);
            wmma::load_matrix_sync(bf, sW + (it * 64 + ks) * LDW + wn0, LDW);
#pragma unroll
            for (int i = 0; i < MFRAG; i++)
                wmma::mma_sync(acc[i], af[i], bf, acc[i]);
        }
    }
    cpa_wait<0>();
    __syncthreads();
#pragma unroll
    for (int i = 0; i < MFRAG; i++)
        wmma::store_matrix_sync(sE + (wm0 + 16 * i) * (NC + 4) + wn0, acc[i], NC + 4,
                                wmma::mem_row_major);
    __syncthreads();
#pragma unroll
    for (int e = 0; e < (128 * NC) / 256; e++) {
        const int idx = tid + e * 256;
        const int m = idx / NC;
        const int n = idx % NC;
        epi(m, n, sE[m * (NC + 4) + n]);
    }
    __syncthreads();
}

// ---------------- kernels ----------------

__global__ void zero_h_kernel()
{
    int i = blockIdx.x * blockDim.x + threadIdx.x;
    ((float*)g_h)[i] = 0.0f;
    ((__half*)g_hh)[i] = __float2half(0.0f);
}

struct alignas(8) H4 { __half2 a, b; };
__device__ __forceinline__ H4 f2h4(float4 vv)
{
    H4 o;
    o.a = __floats2half2_rn(vv.x, vv.y);
    o.b = __floats2half2_rn(vv.z, vv.w);
    return o;
}

#define NX4 ((BB * BT * II) / 4)     // 8388608 float4 per direction input
#define NW4 ((II * HH) / 4)          // 131072 float4 per W matrix
#define NO4 ((2 * HH * TGTD) / 4)    // 65536 float4 for Wo

struct ConvArgs {
    const float4* x[2];
    const float4* w[6];
    const float4* wo;
};

// one fused conversion kernel: inputs, input weights, output weights
__global__ void conv_all_kernel(ConvArgs c)
{
    long i = (long)blockIdx.x * blockDim.x + threadIdx.x;
    if (i < 2L * NX4) {
        const int dir = i >= NX4;
        const long k = i - (long)dir * NX4;
        ((H4*)&g_xh[dir][0])[k] = f2h4(c.x[dir][k]);
    } else if (i < 2L * NX4 + 6L * NW4) {
        const long j = i - 2L * NX4;
        const int slot = (int)(j / NW4);
        const long k = j % NW4;
        ((H4*)&g_wh[slot / 3][slot % 3][0])[k] = f2h4(c.w[slot][k]);
    } else {
        const long k = i - 2L * NX4 - 6L * NW4;
        ((H4*)&g_woh[0])[k] = f2h4(c.wo[k]);
    }
}

struct ProjArgs { const float* bias[2][3]; };

// grid (24, 512, 2): 128x128 tiles over [65536 x 3072]
__global__ void __launch_bounds__(256) proj_kernel(ProjArgs a)
{
    const int d  = blockIdx.z;
    const int m0 = blockIdx.y * 128;
    const int n0 = blockIdx.x * 128;
    const int g  = n0 >> 10;
    const int nb = n0 & 1023;
    const __half* X  = g_xh[d];
    const __half* Bp = g_wh[d][g] + nb;
    const float*  bs = a.bias[d][g];

    auto rowA = [&](int m) -> const __half* {
        const int rr = m0 + m;
        const int t = rr >> 7;
        const int b = rr & 127;
        return X + ((size_t)b * BT + t) * II;
    };
    auto epi = [&](int m, int n, float vv) {
        const int rr = m0 + m;
        const int c = nb + n;
        g_xp[d][g][rr][c] = __float2half(vv + bs[c]);
    };
    gemm128(II, rowA, Bp, HH, epi);
}

struct RecArgs { const float* U[2][2]; const float* Uh[2]; };

// Dynamic smem layout for recur_kernel:
//   [0      , 81920 )  sW1: 1024 x 32 fp16, padded row stride 40 halves
//   [81920  , 131072)  sW2: 1024 x 16 fp16, padded row stride 24 halves
//   [131072 , 204800)  sA : 4 stages x 128 x 72 fp16   (sE fp32 staging aliases here)
//   [204800 , 212992)  sX : xg/xh tile
//   [212992 , 221184)  sY : hh tile (phase1) / u tile fp32 (phase2)
//   [221184 , 229376)  sZ : h tile fp32 (phase2)
#define REC_SMEM 229376
__global__ void __launch_bounds__(256) recur_kernel(RecArgs a)
{
    extern __shared__ __align__(16) char rsm[];
    __half* sW1 = (__half*)rsm;
    __half* sW2 = (__half*)(rsm + 81920);
    __half* sA  = (__half*)(rsm + 131072);
    float*  sE  = (float*)(rsm + 131072);
    __half* sXh = (__half*)(rsm + 204800);
    __half* sYh = (__half*)(rsm + 212992);
    float*  sU  = (float*)(rsm + 212992);
    float*  sHf = (float*)(rsm + 221184);

    const uint32_t sX_a = (uint32_t)__cvta_generic_to_shared(sXh);
    const uint32_t sY_a = (uint32_t)__cvta_generic_to_shared(sYh);
    const uint32_t sZ_a = (uint32_t)__cvta_generic_to_shared(sHf);

    const int tid = threadIdx.x;
    const int s = blockIdx.x & 63;
    const int d = blockIdx.x >> 6;
    const int g1 = s >> 5;                             // phase1 gate (0=r,1=u)
    const int col0 = (s & 31) * 32;                    // phase1 col base
    const int col2 = s * 16;                           // phase2 col base

    // Load weight slices into smem (fp32 -> fp16), once. Padded strides.
    {
        const float* src1 = a.U[d][g1];
#pragma unroll
        for (int i = 0; i < 32; i++) {
            const int idx = tid + i * 256;
            const int k = idx >> 3, q = idx & 7;
            float4 w = *(const float4*)(src1 + (size_t)k * HH + col0 + q * 4);
            *(__half2*)(sW1 + k * 40 + q * 4)     = __floats2half2_rn(w.x, w.y);
            *(__half2*)(sW1 + k * 40 + q * 4 + 2) = __floats2half2_rn(w.z, w.w);
        }
        const float* src2 = a.Uh[d];
#pragma unroll
        for (int i = 0; i < 16; i++) {
            const int idx = tid + i * 256;
            const int k = idx >> 2, q = idx & 3;
            float4 w = *(const float4*)(src2 + (size_t)k * HH + col2 + q * 4);
            *(__half2*)(sW2 + k * 24 + q * 4)     = __floats2half2_rn(w.x, w.y);
            *(__half2*)(sW2 + k * 24 + q * 4 + 2) = __floats2half2_rn(w.z, w.w);
        }
    }
    __syncthreads();

    for (int t = 0; t < BT; ++t) {
        {   // ---- phase 1 ----
            const __half* xg = &g_xp[d][g1][(size_t)t * BB][0];
            // epilogue operand prefetch (group 0): xg tile, hh tile (gate r only)
            {
#pragma unroll
                for (int rep = 0; rep < 2; rep++) {
                    const int idx = tid + rep * 256;
                    const int row = idx >> 2, q = idx & 3;
                    cpa16(sX_a + (uint32_t)(row * 64 + q * 16),
                          xg + (size_t)row * HH + col0 + q * 8);
                    if (g1 == 0)
                        cpa16(sY_a + (uint32_t)(row * 64 + q * 16),
                              &g_hh[d][row][col0] + q * 8);
                }
                cpa_commit();
            }
            auto epi = [&](int m, int n, float vv) {
                const int c = col0 + n;
                const float sg = sigmoidf_(__half2float(sXh[m * 32 + n]) + vv);
                if (g1 == 0)
                    g_rhh[d][m][c] = __float2half(sg * __half2float(sYh[m * 32 + n]));
                else
                    g_u[d][m][c] = sg;
            };
            rec_phase<32, 40, 2>(&g_hh[d][0][0], sW1, sA, sE, epi);
        }
        dir_barrier(d);
        {   // ---- phase 2 ----
            const __half* xh = &g_xp[d][2][(size_t)t * BB][0];
            {   // prefetch xh (128x16 fp16), u (128x16 fp32), h (128x16 fp32)
                {
                    const int row = tid >> 1, q = tid & 1;
                    cpa16(sX_a + (uint32_t)(row * 32 + q * 16),
                          xh + (size_t)row * HH + col2 + q * 8);
                }
#pragma unroll
                for (int rep = 0; rep < 2; rep++) {
                    const int idx = tid + rep * 256;
                    const int row = idx >> 2, q = idx & 3;
                    cpa16(sY_a + (uint32_t)(row * 64 + q * 16),
                          &g_u[d][row][col2] + q * 4);
                    cpa16(sZ_a + (uint32_t)(row * 64 + q * 16),
                          &g_h[d][row][col2] + q * 4);
                }
                cpa_commit();
            }
            auto epi = [&](int m, int n, float vv) {
                const int c = col2 + n;
                const float cand = tanhf(__half2float(sXh[m * 16 + n]) + vv);
                const float uu = sU[m * 16 + n];
                const float hp = sHf[m * 16 + n];
                const float hn = uu * hp + (1.0f - uu) * cand;
                g_h[d][m][c] = hn;
                const __half hhv = __float2half(hn);
                g_hh[d][m][c] = hhv;
                g_hcat[(size_t)t * BB + m][d * HH + c] = hhv;
            };
            rec_phase<16, 24, 1>(&g_rhh[d][0][0], sW2, sA, sE, epi);
        }
        dir_barrier(d);
    }
}

// grid (1, 512)
__global__ void __launch_bounds__(256) out_kernel(const float* __restrict__ bo,
                                                  float* __restrict__ out)
{
    const int m0 = blockIdx.y * 128;
    const __half* Bp = g_woh;

    auto rowA = [&](int m) -> const __half* { return &g_hcat[m0 + m][0]; };
    auto epi = [&](int m, int n, float vv) {
        out[(size_t)(m0 + m) * TGTD + n] = sigmoidf_(vv + bo[n]);
    };
    gemm128(2 * HH, rowA, Bp, TGTD, epi);
}

// ---------------- launch ----------------
extern "C" void kernel_launch(void* const* d_in, const int* in_sizes, int n_in,
                              void* d_out, int out_size)
{
    (void)in_sizes; (void)n_in; (void)out_size;
    const float* fwd = (const float*)d_in[0];
    const float* bwd = (const float*)d_in[1];
    const float* Wr  = (const float*)d_in[2];
    const float* Ur  = (const float*)d_in[3];
    const float* br  = (const float*)d_in[4];
    const float* Wu  = (const float*)d_in[5];
    const float* Uu  = (const float*)d_in[6];
    const float* bu  = (const float*)d_in[7];
    const float* Wh  = (const float*)d_in[8];
    const float* Uh  = (const float*)d_in[9];
    const float* bh  = (const float*)d_in[10];
    const float* Wr1 = (const float*)d_in[11];
    const float* Ur1 = (const float*)d_in[12];
    const float* br1 = (const float*)d_in[13];
    const float* Wu1 = (const float*)d_in[14];
    const float* Uu1 = (const float*)d_in[15];
    const float* bu1 = (const float*)d_in[16];
    const float* Wh1 = (const float*)d_in[17];
    const float* Uh1 = (const float*)d_in[18];
    const float* bh1 = (const float*)d_in[19];
    const float* Wo  = (const float*)d_in[20];
    const float* bo  = (const float*)d_in[21];
    float* out = (float*)d_out;

    static bool attr_done = false;
    if (!attr_done) {
        cudaFuncSetAttribute(recur_kernel, cudaFuncAttributeMaxDynamicSharedMemorySize,
                             REC_SMEM);
        cudaFuncSetAttribute(proj_kernel, cudaFuncAttributeMaxDynamicSharedMemorySize,
                             GEMM128_SMEM);
        cudaFuncSetAttribute(out_kernel, cudaFuncAttributeMaxDynamicSharedMemorySize,
                             GEMM128_SMEM);
        attr_done = true;
    }

    // my launch #1
    zero_h_kernel<<<(2 * BB * HH) / 1024, 1024>>>();

    // my launch #2: fused conversions
    {
        ConvArgs c;
        c.x[0] = (const float4*)fwd;
        c.x[1] = (const float4*)bwd;
        c.w[0] = (const float4*)Wr;  c.w[1] = (const float4*)Wu;  c.w[2] = (const float4*)Wh;
        c.w[3] = (const float4*)Wr1; c.w[4] = (const float4*)Wu1; c.w[5] = (const float4*)Wh1;
        c.wo = (const float4*)Wo;
        const long total = 2L * NX4 + 6L * NW4 + NO4;   // 17629184
        conv_all_kernel<<<(unsigned)(total / 256), 256>>>(c);
    }

    // my launch #3
    ProjArgs pa;
    pa.bias[0][0] = br;  pa.bias[0][1] = bu;  pa.bias[0][2] = bh;
    pa.bias[1][0] = br1; pa.bias[1][1] = bu1; pa.bias[1][2] = bh1;
    proj_kernel<<<dim3(3 * HH / 128, MROWS / 128, 2), 256, GEMM128_SMEM>>>(pa);

    // my launch #4 (= overall #6 given 2 harness-internal launches): the recurrence
    RecArgs ra;
    ra.U[0][0] = Ur;  ra.U[0][1] = Uu;
    ra.U[1][0] = Ur1; ra.U[1][1] = Uu1;
    ra.Uh[0] = Uh; ra.Uh[1] = Uh1;
    recur_kernel<<<NBLK, 256, REC_SMEM>>>(ra);

    // my launch #5
    out_kernel<<<dim3(1, MROWS / 128, 1), 256, GEMM128_SMEM>>>(bo, out);
}